// round 10
// baseline (speedup 1.0000x reference)
#include <cuda_runtime.h>
#include <cstdint>

#define B_   4
#define N_   4096
#define FIN  256
#define FOUT 128
#define MTOT (B_ * N_)   // 16384

// ---------------- device scratch (no-alloc rule) ----------------
__device__ float g_Wh[(size_t)MTOT * FOUT];   // tf32-rounded values, [row][o]
__device__ float g_src[MTOT];
__device__ float g_dst[MTOT];

// ---------------- helpers ----------------
__device__ __forceinline__ uint32_t f2tf32(float v) {
    uint32_t r;
    asm("cvt.rna.tf32.f32 %0, %1;" : "=r"(r) : "f"(v));
    return r;
}
__device__ __forceinline__ void mma_tf32(float* d, const uint32_t* a, const uint32_t* b) {
    asm volatile(
        "mma.sync.aligned.m16n8k8.row.col.f32.tf32.tf32.f32 "
        "{%0,%1,%2,%3}, {%4,%5,%6,%7}, {%8,%9}, {%0,%1,%2,%3};"
        : "+f"(d[0]), "+f"(d[1]), "+f"(d[2]), "+f"(d[3])
        : "r"(a[0]), "r"(a[1]), "r"(a[2]), "r"(a[3]), "r"(b[0]), "r"(b[1]));
}
__device__ __forceinline__ void cp16(uint32_t smem_addr, const void* gptr) {
    asm volatile("cp.async.cg.shared.global [%0], [%1], 16;"
                 :: "r"(smem_addr), "l"(gptr));
}
__device__ __forceinline__ void cp_commit() {
    asm volatile("cp.async.commit_group;" ::: "memory");
}
__device__ __forceinline__ void cp_wait0() {
    asm volatile("cp.async.wait_group 0;" ::: "memory");
}

// ============================================================
// Kernel 1: Wh = h @ W^T + b ; store tf32-rounded Wh + src/dst
// ============================================================
__global__ void __launch_bounds__(256) k_gemm(
    const float* __restrict__ h, const float* __restrict__ Ww,
    const float* __restrict__ Wb, const float* __restrict__ aw)
{
    __shared__ float hs[32][68];
    __shared__ float ws[32][132];

    const int t  = threadIdx.x;
    const int r0 = blockIdx.x * 64;
    const int to = t & 15, ti = t >> 4;
    const int i0 = ti * 4, o0 = to * 4;

    float acc[4][8];
#pragma unroll
    for (int a = 0; a < 4; a++)
#pragma unroll
        for (int c = 0; c < 8; c++) acc[a][c] = 0.f;

    const int hi = t >> 2, hkb = (t & 3) * 8;
    const int wo = t >> 1, wkb = (t & 1) * 16;

    for (int kt = 0; kt < FIN; kt += 32) {
        const float* hp = h + (size_t)(r0 + hi) * FIN + kt + hkb;
        float4 ha = *(const float4*)(hp);
        float4 hb = *(const float4*)(hp + 4);
        const float* wp = Ww + (size_t)wo * FIN + kt + wkb;
        float4 wa  = *(const float4*)(wp);
        float4 wb4 = *(const float4*)(wp + 4);
        float4 wc  = *(const float4*)(wp + 8);
        float4 wd  = *(const float4*)(wp + 12);

        __syncthreads();

        hs[hkb + 0][hi] = ha.x; hs[hkb + 1][hi] = ha.y;
        hs[hkb + 2][hi] = ha.z; hs[hkb + 3][hi] = ha.w;
        hs[hkb + 4][hi] = hb.x; hs[hkb + 5][hi] = hb.y;
        hs[hkb + 6][hi] = hb.z; hs[hkb + 7][hi] = hb.w;

        ws[wkb +  0][wo] = wa.x;  ws[wkb +  1][wo] = wa.y;
        ws[wkb +  2][wo] = wa.z;  ws[wkb +  3][wo] = wa.w;
        ws[wkb +  4][wo] = wb4.x; ws[wkb +  5][wo] = wb4.y;
        ws[wkb +  6][wo] = wb4.z; ws[wkb +  7][wo] = wb4.w;
        ws[wkb +  8][wo] = wc.x;  ws[wkb +  9][wo] = wc.y;
        ws[wkb + 10][wo] = wc.z;  ws[wkb + 11][wo] = wc.w;
        ws[wkb + 12][wo] = wd.x;  ws[wkb + 13][wo] = wd.y;
        ws[wkb + 14][wo] = wd.z;  ws[wkb + 15][wo] = wd.w;

        __syncthreads();

#pragma unroll 8
        for (int kk = 0; kk < 32; kk++) {
            float4 a4 = *(const float4*)&hs[kk][i0];
            float4 b0 = *(const float4*)&ws[kk][o0];
            float4 b1 = *(const float4*)&ws[kk][o0 + 64];
            float av[4] = {a4.x, a4.y, a4.z, a4.w};
            float bv[8] = {b0.x, b0.y, b0.z, b0.w, b1.x, b1.y, b1.z, b1.w};
#pragma unroll
            for (int ii = 0; ii < 4; ii++)
#pragma unroll
                for (int oo = 0; oo < 8; oo++)
                    acc[ii][oo] = fmaf(av[ii], bv[oo], acc[ii][oo]);
        }
    }

    float bo[8], asv[8], adv[8];
#pragma unroll
    for (int oo = 0; oo < 8; oo++) {
        int o = (oo < 4) ? (o0 + oo) : (64 + o0 + oo - 4);
        bo[oo]  = Wb[o];
        asv[oo] = aw[o];
        adv[oo] = aw[FOUT + o];
    }
    float sp[4], dp[4];
#pragma unroll
    for (int ii = 0; ii < 4; ii++) {
        float s = 0.f, d = 0.f;
        float v[8];
#pragma unroll
        for (int oo = 0; oo < 8; oo++) {
            v[oo] = acc[ii][oo] + bo[oo];
            s = fmaf(v[oo], asv[oo], s);
            d = fmaf(v[oo], adv[oo], d);
        }
        sp[ii] = s; dp[ii] = d;
        const int row = r0 + i0 + ii;
        *(float4*)&g_Wh[(size_t)row * FOUT + o0] =
            make_float4(__uint_as_float(f2tf32(v[0])), __uint_as_float(f2tf32(v[1])),
                        __uint_as_float(f2tf32(v[2])), __uint_as_float(f2tf32(v[3])));
        *(float4*)&g_Wh[(size_t)row * FOUT + 64 + o0] =
            make_float4(__uint_as_float(f2tf32(v[4])), __uint_as_float(f2tf32(v[5])),
                        __uint_as_float(f2tf32(v[6])), __uint_as_float(f2tf32(v[7])));
    }
#pragma unroll
    for (int off = 8; off >= 1; off >>= 1)
#pragma unroll
        for (int ii = 0; ii < 4; ii++) {
            sp[ii] += __shfl_down_sync(0xffffffffu, sp[ii], off);
            dp[ii] += __shfl_down_sync(0xffffffffu, dp[ii], off);
        }
    if (to == 0)
#pragma unroll
        for (int ii = 0; ii < 4; ii++) {
            g_src[r0 + i0 + ii] = sp[ii];
            g_dst[r0 + i0 + ii] = dp[ii];
        }
}

// ============================================================
// Kernel 2: attention via warp-level tf32 mma.sync.
// CTA: 128 rows x 128 cols, 512 threads / 16 warps (32x32 MMA tiles).
// Coalesced adj producer mapping (R9). Double-buffered A/B, one
// __syncthreads per chunk; B tiles filled by cp.async.
//   iter c: cp.async B(c+1) + LDG adj(c+1) -> MMA(buf c)
//           -> exp/STS A(c+1) into buf c^1 -> wait cp -> sync
// ============================================================
#define KC     64
#define STRA   68                         // A tile stride (floats): 68 % 32 == 4
#define STRB   136                        // B tile stride (floats)
#define ABYT   (128 * STRA * 4)           // 34816
#define BBYT   (KC * STRB * 4)            // 34816
#define SM_DST 0                          // 4096 f = 16384 B
#define SM_DEN 16384                      // 128 f
#define SM_A0  17408
#define SM_A1  (SM_A0 + ABYT)
#define SM_B0  (SM_A1 + ABYT)
#define SM_B1  (SM_B0 + BBYT)
#define SMEM_SZ (SM_B1 + BBYT)            // 156672

__global__ void __launch_bounds__(512, 1) k_attn(
    const int* __restrict__ adj, const float* __restrict__ abp,
    float* __restrict__ out)
{
    extern __shared__ char sm[];
    float*    dst_s = (float*)(sm + SM_DST);
    float*    den_s = (float*)(sm + SM_DEN);
    uint32_t* Ab[2] = { (uint32_t*)(sm + SM_A0), (uint32_t*)(sm + SM_A1) };
    uint32_t* Bb[2] = { (uint32_t*)(sm + SM_B0), (uint32_t*)(sm + SM_B1) };
    const uint32_t smem_u32 = (uint32_t)__cvta_generic_to_shared(sm);

    const int t    = threadIdx.x;
    const int w    = t >> 5, lane = t & 31;
    const int rg0  = blockIdx.x * 128;
    const int b    = rg0 >> 12;
    const int bN   = b << 12;
    const int wr0  = w * 8;                 // this warp's 8 rows
    const int cl   = 2 * lane;              // this lane's 2 cols per chunk

    // stage dst for this batch
    {
        const float4* g  = (const float4*)(g_dst + bN);
        float4*       d4 = (float4*)dst_s;
        for (int q = t; q < N_ / 4; q += 512) d4[q] = g[q];
    }

    const float ab = *abp;
    float srcA[8];
#pragma unroll
    for (int rr = 0; rr < 8; rr++) srcA[rr] = g_src[rg0 + wr0 + rr] + ab;

    // B copy mapping: thread -> Wh row bj (0..63), float4 col bc (0..7)
    const int bj = t >> 3, bc = t & 7;
    const float* whg = g_Wh + (size_t)(bN + bj) * FOUT + bc * 4;
    // smem byte offsets (within a B buffer) of this thread's 4 targets
    uint32_t bOff[4];
#pragma unroll
    for (int q = 0; q < 4; q++)
        bOff[q] = (uint32_t)((bj * STRB + (bc + 8 * q) * 4) * 4);

    // mma mapping: 16 warps, 4x4 grid of 32x32 tiles
    const int m0 = (w >> 2) * 32, n0 = (w & 3) * 32;
    const int lr = lane >> 2, lq = lane & 3;

    float acc[8][4];
#pragma unroll
    for (int x = 0; x < 8; x++)
#pragma unroll
        for (int y = 0; y < 4; y++) acc[x][y] = 0.f;
    float denp[8];
#pragma unroll
    for (int rr = 0; rr < 8; rr++) denp[rr] = 0.f;

    // ---------- prologue: chunk 0 ----------
    // B(0) via cp.async into Bb[0]
#pragma unroll
    for (int q = 0; q < 4; q++)
        cp16(smem_u32 + SM_B0 + bOff[q], whg + q * 32);
    cp_commit();

    // adj(0)
    int2 mA[8];
#pragma unroll
    for (int rr = 0; rr < 8; rr++)
        mA[rr] = *(const int2*)(adj + (size_t)(rg0 + wr0 + rr) * N_ + cl);

    __syncthreads();   // dst_s ready

    // produce A(0) into Ab[0]
#pragma unroll
    for (int rr = 0; rr < 8; rr++) {
        float2 dv = *(const float2*)&dst_s[cl];
        float e0 = srcA[rr] + dv.x, e1 = srcA[rr] + dv.y;
        e0 = (e0 >= 0.f) ? e0 : 0.01f * e0;
        e1 = (e1 >= 0.f) ? e1 : 0.01f * e1;
        float w0 = (mA[rr].x > 0) ? __expf(e0) : 0.f;
        float w1 = (mA[rr].y > 0) ? __expf(e1) : 0.f;
        denp[rr] += w0 + w1;
        *(uint2*)&Ab[0][(wr0 + rr) * STRA + cl] = make_uint2(f2tf32(w0), f2tf32(w1));
    }
    cp_wait0();
    __syncthreads();

    // ---------- pipelined main loop ----------
    for (int c = 0; c < N_ / KC; c++) {
        const int buf = c & 1;
        const bool more = (c < N_ / KC - 1);

        // 1) issue next chunk's loads
        if (more) {
            const uint32_t bdst = smem_u32 + (buf ? SM_B0 : SM_B1);
            const float* wsrc = whg + (size_t)(c + 1) * KC * FOUT;
#pragma unroll
            for (int q = 0; q < 4; q++)
                cp16(bdst + bOff[q], wsrc + q * 32);
            cp_commit();
#pragma unroll
            for (int rr = 0; rr < 8; rr++)
                mA[rr] = *(const int2*)(adj + (size_t)(rg0 + wr0 + rr) * N_ + (c + 1) * KC + cl);
        }

        // 2) MMA on buffer c
        {
            const uint32_t* As = Ab[buf];
            const uint32_t* Bs = Bb[buf];
#pragma unroll
            for (int kk = 0; kk < 8; kk++) {
                uint32_t bf[4][2];
#pragma unroll
                for (int nt = 0; nt < 4; nt++) {
                    int o = n0 + nt * 8 + lr;
                    bf[nt][0] = Bs[(kk * 8 + lq) * STRB + o];
                    bf[nt][1] = Bs[(kk * 8 + lq + 4) * STRB + o];
                }
#pragma unroll
                for (int mt = 0; mt < 2; mt++) {
                    uint32_t af[4];
                    int m = m0 + mt * 16 + lr;
                    af[0] = As[m * STRA + kk * 8 + lq];
                    af[1] = As[(m + 8) * STRA + kk * 8 + lq];
                    af[2] = As[m * STRA + kk * 8 + lq + 4];
                    af[3] = As[(m + 8) * STRA + kk * 8 + lq + 4];
#pragma unroll
                    for (int nt = 0; nt < 4; nt++)
                        mma_tf32(acc[mt * 4 + nt], af, bf[nt]);
                }
            }
        }

        // 3) produce A(c+1) into the other buffer
        if (more) {
            uint32_t* As = Ab[buf ^ 1];
            float2 dv = *(const float2*)&dst_s[(c + 1) * KC + cl];
#pragma unroll
            for (int rr = 0; rr < 8; rr++) {
                float e0 = srcA[rr] + dv.x, e1 = srcA[rr] + dv.y;
                e0 = (e0 >= 0.f) ? e0 : 0.01f * e0;
                e1 = (e1 >= 0.f) ? e1 : 0.01f * e1;
                float w0 = (mA[rr].x > 0) ? __expf(e0) : 0.f;
                float w1 = (mA[rr].y > 0) ? __expf(e1) : 0.f;
                denp[rr] += w0 + w1;
                *(uint2*)&As[(wr0 + rr) * STRA + cl] = make_uint2(f2tf32(w0), f2tf32(w1));
            }
            cp_wait0();
        }
        __syncthreads();
    }

    // ---- den: full warp reduce (each row's cols live in one warp) ----
#pragma unroll
    for (int rr = 0; rr < 8; rr++) {
#pragma unroll
        for (int off = 16; off >= 1; off >>= 1)
            denp[rr] += __shfl_xor_sync(0xffffffffu, denp[rr], off);
        if (lane == rr) den_s[wr0 + rr] = denp[rr];
    }
    __syncthreads();

    // ---- epilogue: divide by den, store ----
#pragma unroll
    for (int mt = 0; mt < 2; mt++) {
        int r0 = m0 + mt * 16 + lr;
        int r1 = r0 + 8;
        float inv0 = 1.0f / den_s[r0];
        float inv1 = 1.0f / den_s[r1];
        float* op0 = out + (size_t)(rg0 + r0) * FOUT;
        float* op1 = out + (size_t)(rg0 + r1) * FOUT;
#pragma unroll
        for (int nt = 0; nt < 4; nt++) {
            int col = n0 + nt * 8 + lq * 2;
            *(float2*)(op0 + col) = make_float2(acc[mt * 4 + nt][0] * inv0,
                                                acc[mt * 4 + nt][1] * inv0);
            *(float2*)(op1 + col) = make_float2(acc[mt * 4 + nt][2] * inv1,
                                                acc[mt * 4 + nt][3] * inv1);
        }
    }
}

extern "C" void kernel_launch(void* const* d_in, const int* in_sizes, int n_in,
                              void* d_out, int out_size) {
    const float* h   = (const float*)d_in[0];
    const int*   adj = (const int*)d_in[1];
    const float* Ww  = (const float*)d_in[2];
    const float* Wb  = (const float*)d_in[3];
    const float* aw  = (const float*)d_in[4];
    const float* abp = (const float*)d_in[5];
    float* outp = (float*)d_out;

    cudaFuncSetAttribute(k_attn, cudaFuncAttributeMaxDynamicSharedMemorySize, SMEM_SZ);

    k_gemm<<<MTOT / 64, 256>>>(h, Ww, Wb, aw);
    k_attn<<<MTOT / 128, 512, SMEM_SZ>>>(adj, abp, outp);
}

// round 11
// speedup vs baseline: 1.0203x; 1.0203x over previous
#include <cuda_runtime.h>
#include <cstdint>

#define B_   4
#define N_   4096
#define FIN  256
#define FOUT 128
#define MTOT (B_ * N_)   // 16384

// ---------------- device scratch (no-alloc rule) ----------------
__device__ float g_Wh[(size_t)MTOT * FOUT];   // tf32-rounded values, [row][o]
__device__ float g_src[MTOT];
__device__ float g_dst[MTOT];

// ---------------- helpers ----------------
__device__ __forceinline__ uint32_t f2tf32(float v) {
    uint32_t r;
    asm("cvt.rna.tf32.f32 %0, %1;" : "=r"(r) : "f"(v));
    return r;
}
__device__ __forceinline__ void mma_tf32(float* d, const uint32_t* a, const uint32_t* b) {
    asm volatile(
        "mma.sync.aligned.m16n8k8.row.col.f32.tf32.tf32.f32 "
        "{%0,%1,%2,%3}, {%4,%5,%6,%7}, {%8,%9}, {%0,%1,%2,%3};"
        : "+f"(d[0]), "+f"(d[1]), "+f"(d[2]), "+f"(d[3])
        : "r"(a[0]), "r"(a[1]), "r"(a[2]), "r"(a[3]), "r"(b[0]), "r"(b[1]));
}
__device__ __forceinline__ void barg(int id) {
    asm volatile("bar.sync %0, 256;" :: "r"(id) : "memory");
}

// ============================================================
// Kernel 1: Wh = h @ W^T + b ; store tf32-rounded Wh + src/dst
// ============================================================
__global__ void __launch_bounds__(256) k_gemm(
    const float* __restrict__ h, const float* __restrict__ Ww,
    const float* __restrict__ Wb, const float* __restrict__ aw)
{
    __shared__ float hs[32][68];
    __shared__ float ws[32][132];

    const int t  = threadIdx.x;
    const int r0 = blockIdx.x * 64;
    const int to = t & 15, ti = t >> 4;
    const int i0 = ti * 4, o0 = to * 4;

    float acc[4][8];
#pragma unroll
    for (int a = 0; a < 4; a++)
#pragma unroll
        for (int c = 0; c < 8; c++) acc[a][c] = 0.f;

    const int hi = t >> 2, hkb = (t & 3) * 8;
    const int wo = t >> 1, wkb = (t & 1) * 16;

    for (int kt = 0; kt < FIN; kt += 32) {
        const float* hp = h + (size_t)(r0 + hi) * FIN + kt + hkb;
        float4 ha = *(const float4*)(hp);
        float4 hb = *(const float4*)(hp + 4);
        const float* wp = Ww + (size_t)wo * FIN + kt + wkb;
        float4 wa  = *(const float4*)(wp);
        float4 wb4 = *(const float4*)(wp + 4);
        float4 wc  = *(const float4*)(wp + 8);
        float4 wd  = *(const float4*)(wp + 12);

        __syncthreads();

        hs[hkb + 0][hi] = ha.x; hs[hkb + 1][hi] = ha.y;
        hs[hkb + 2][hi] = ha.z; hs[hkb + 3][hi] = ha.w;
        hs[hkb + 4][hi] = hb.x; hs[hkb + 5][hi] = hb.y;
        hs[hkb + 6][hi] = hb.z; hs[hkb + 7][hi] = hb.w;

        ws[wkb +  0][wo] = wa.x;  ws[wkb +  1][wo] = wa.y;
        ws[wkb +  2][wo] = wa.z;  ws[wkb +  3][wo] = wa.w;
        ws[wkb +  4][wo] = wb4.x; ws[wkb +  5][wo] = wb4.y;
        ws[wkb +  6][wo] = wb4.z; ws[wkb +  7][wo] = wb4.w;
        ws[wkb +  8][wo] = wc.x;  ws[wkb +  9][wo] = wc.y;
        ws[wkb + 10][wo] = wc.z;  ws[wkb + 11][wo] = wc.w;
        ws[wkb + 12][wo] = wd.x;  ws[wkb + 13][wo] = wd.y;
        ws[wkb + 14][wo] = wd.z;  ws[wkb + 15][wo] = wd.w;

        __syncthreads();

#pragma unroll 8
        for (int kk = 0; kk < 32; kk++) {
            float4 a4 = *(const float4*)&hs[kk][i0];
            float4 b0 = *(const float4*)&ws[kk][o0];
            float4 b1 = *(const float4*)&ws[kk][o0 + 64];
            float av[4] = {a4.x, a4.y, a4.z, a4.w};
            float bv[8] = {b0.x, b0.y, b0.z, b0.w, b1.x, b1.y, b1.z, b1.w};
#pragma unroll
            for (int ii = 0; ii < 4; ii++)
#pragma unroll
                for (int oo = 0; oo < 8; oo++)
                    acc[ii][oo] = fmaf(av[ii], bv[oo], acc[ii][oo]);
        }
    }

    float bo[8], asv[8], adv[8];
#pragma unroll
    for (int oo = 0; oo < 8; oo++) {
        int o = (oo < 4) ? (o0 + oo) : (64 + o0 + oo - 4);
        bo[oo]  = Wb[o];
        asv[oo] = aw[o];
        adv[oo] = aw[FOUT + o];
    }
    float sp[4], dp[4];
#pragma unroll
    for (int ii = 0; ii < 4; ii++) {
        float s = 0.f, d = 0.f;
        float v[8];
#pragma unroll
        for (int oo = 0; oo < 8; oo++) {
            v[oo] = acc[ii][oo] + bo[oo];
            s = fmaf(v[oo], asv[oo], s);
            d = fmaf(v[oo], adv[oo], d);
        }
        sp[ii] = s; dp[ii] = d;
        const int row = r0 + i0 + ii;
        *(float4*)&g_Wh[(size_t)row * FOUT + o0] =
            make_float4(__uint_as_float(f2tf32(v[0])), __uint_as_float(f2tf32(v[1])),
                        __uint_as_float(f2tf32(v[2])), __uint_as_float(f2tf32(v[3])));
        *(float4*)&g_Wh[(size_t)row * FOUT + 64 + o0] =
            make_float4(__uint_as_float(f2tf32(v[4])), __uint_as_float(f2tf32(v[5])),
                        __uint_as_float(f2tf32(v[6])), __uint_as_float(f2tf32(v[7])));
    }
#pragma unroll
    for (int off = 8; off >= 1; off >>= 1)
#pragma unroll
        for (int ii = 0; ii < 4; ii++) {
            sp[ii] += __shfl_down_sync(0xffffffffu, sp[ii], off);
            dp[ii] += __shfl_down_sync(0xffffffffu, dp[ii], off);
        }
    if (to == 0)
#pragma unroll
        for (int ii = 0; ii < 4; ii++) {
            g_src[r0 + i0 + ii] = sp[ii];
            g_dst[r0 + i0 + ii] = dp[ii];
        }
}

// ============================================================
// Kernel 2: attention via warp-level tf32 mma.sync.
// CTA: 128 rows x 128 cols, 512 threads. Split into TWO independent
// barrier groups of 8 warps (named barriers): group g owns rows
// g*64..g*64+63, private A/B tiles, chunk order rotated by 32.
// Per-warp code identical to R9 (best measured).
// ============================================================
#define KC     64
#define STRA   68                         // A tile stride (floats): 68 % 32 == 4
#define STRB   136                        // B tile stride (floats)
#define ATILE  (64 * STRA * 4)            // 17408 B per group
#define BTILE  (KC * STRB * 4)            // 34816 B per group
#define SM_DST 0                          // 4096 f = 16384 B
#define SM_DEN 16384                      // 128 f = 512 B
#define SM_A0  16896
#define SM_A1  (SM_A0 + ATILE)
#define SM_B0  (SM_A1 + ATILE)
#define SM_B1  (SM_B0 + BTILE)
#define SMEM_SZ (SM_B1 + BTILE)           // 121344

__global__ void __launch_bounds__(512, 1) k_attn(
    const int* __restrict__ adj, const float* __restrict__ abp,
    float* __restrict__ out)
{
    extern __shared__ char sm[];
    float* dst_s = (float*)(sm + SM_DST);
    float* den_s = (float*)(sm + SM_DEN);

    const int t    = threadIdx.x;
    const int w    = t >> 5, lane = t & 31;
    const int g    = w >> 3;                // barrier group 0/1
    const int wg   = w & 7;                 // warp within group
    const int tg   = t & 255;               // thread within group
    const int rg0  = blockIdx.x * 128;
    const int b    = rg0 >> 12;
    const int bN   = b << 12;

    uint32_t* As = (uint32_t*)(sm + (g ? SM_A1 : SM_A0));   // [m][k] group tile
    uint32_t* Bs = (uint32_t*)(sm + (g ? SM_B1 : SM_B0));   // [k][o] group tile
    const int bid = 1 + g;                  // named barrier id

    const int wr0 = g * 64 + wg * 8;        // this warp's 8 rows (CTA-local)
    const int cl  = 2 * lane;               // this lane's 2 cols per chunk

    // stage dst for this batch (all 512 threads)
    {
        const float4* gp = (const float4*)(g_dst + bN);
        float4*       d4 = (float4*)dst_s;
        for (int q = t; q < N_ / 4; q += 512) d4[q] = gp[q];
    }

    const float ab = *abp;
    float srcA[8];
#pragma unroll
    for (int rr = 0; rr < 8; rr++) srcA[rr] = g_src[rg0 + wr0 + rr] + ab;

    // B copy mapping (within group): thread -> Wh row bj (0..63), float4 col bc (0..3)
    const int bj = tg >> 2, bc = tg & 3;
    const float4* whp = (const float4*)(g_Wh + (size_t)(bN + bj) * FOUT) + bc;

    // mma mapping (within group): 8 warps, 2x4 grid of 32x32 tiles
    const int m0g = (wg >> 2) * 32;          // group-local row base of warp tile
    const int m0  = g * 64 + m0g;            // CTA-local
    const int n0  = (wg & 3) * 32;
    const int lr = lane >> 2, lq = lane & 3;

    float acc[8][4];
#pragma unroll
    for (int x = 0; x < 8; x++)
#pragma unroll
        for (int y = 0; y < 4; y++) acc[x][y] = 0.f;
    float denp[8];
#pragma unroll
    for (int rr = 0; rr < 8; rr++) denp[rr] = 0.f;

    // prefetch this group's chunk 0 (rotated: group g starts at chunk g*32)
    const int c0 = g * 32;
    int2   mA[8];
    float4 vB[8];
#pragma unroll
    for (int rr = 0; rr < 8; rr++)
        mA[rr] = *(const int2*)(adj + (size_t)(rg0 + wr0 + rr) * N_ + c0 * KC + cl);
#pragma unroll
    for (int q = 0; q < 8; q++)
        vB[q] = whp[(size_t)c0 * KC * (FOUT / 4) + q * 4];

    __syncthreads();   // dst_s ready (both groups)

    for (int c = 0; c < N_ / KC; c++) {
        const int ce = (c + c0) & (N_ / KC - 1);        // this group's chunk
        const int cn = (c + 1 + c0) & (N_ / KC - 1);    // next chunk

        // ---- weights: exp(lrelu(src+dst+ab)), masked; den in fp32 ----
        float2 dv = *(const float2*)&dst_s[ce * KC + cl];
        uint2 wpair[8];
#pragma unroll
        for (int rr = 0; rr < 8; rr++) {
            float e0 = srcA[rr] + dv.x, e1 = srcA[rr] + dv.y;
            e0 = (e0 >= 0.f) ? e0 : 0.01f * e0;
            e1 = (e1 >= 0.f) ? e1 : 0.01f * e1;
            float w0 = (mA[rr].x > 0) ? __expf(e0) : 0.f;
            float w1 = (mA[rr].y > 0) ? __expf(e1) : 0.f;
            denp[rr] += w0 + w1;
            wpair[rr] = make_uint2(f2tf32(w0), f2tf32(w1));
        }

        barg(bid);   // previous chunk's mma reads done (group only)

        // ---- store A (weights) [m][k] and B (Wh) [k][o] (group tiles) ----
#pragma unroll
        for (int rr = 0; rr < 8; rr++)
            *(uint2*)&As[(wg * 8 + rr) * STRA + cl] = wpair[rr];
#pragma unroll
        for (int q = 0; q < 8; q++)
            *(float4*)&Bs[bj * STRB + (bc + 4 * q) * 4] = vB[q];

        // ---- prefetch next chunk (lands during mma) ----
        if (c < N_ / KC - 1) {
#pragma unroll
            for (int rr = 0; rr < 8; rr++)
                mA[rr] = *(const int2*)(adj + (size_t)(rg0 + wr0 + rr) * N_ + cn * KC + cl);
#pragma unroll
            for (int q = 0; q < 8; q++)
                vB[q] = whp[(size_t)cn * KC * (FOUT / 4) + q * 4];
        }

        barg(bid);

        // ---- mma: 8 k-steps of m16n8k8, 32x32 warp tile ----
#pragma unroll
        for (int kk = 0; kk < 8; kk++) {
            uint32_t bf[4][2];
#pragma unroll
            for (int nt = 0; nt < 4; nt++) {
                int o = n0 + nt * 8 + lr;
                bf[nt][0] = Bs[(kk * 8 + lq) * STRB + o];
                bf[nt][1] = Bs[(kk * 8 + lq + 4) * STRB + o];
            }
#pragma unroll
            for (int mt = 0; mt < 2; mt++) {
                uint32_t af[4];
                int m = m0g + mt * 16 + lr;
                af[0] = As[m * STRA + kk * 8 + lq];
                af[1] = As[(m + 8) * STRA + kk * 8 + lq];
                af[2] = As[m * STRA + kk * 8 + lq + 4];
                af[3] = As[(m + 8) * STRA + kk * 8 + lq + 4];
#pragma unroll
                for (int nt = 0; nt < 4; nt++)
                    mma_tf32(acc[mt * 4 + nt], af, bf[nt]);
            }
        }
    }

    // ---- den: full warp reduce (each row's cols live in one warp) ----
#pragma unroll
    for (int rr = 0; rr < 8; rr++) {
#pragma unroll
        for (int off = 16; off >= 1; off >>= 1)
            denp[rr] += __shfl_xor_sync(0xffffffffu, denp[rr], off);
        if (lane == rr) den_s[wr0 + rr] = denp[rr];
    }
    barg(bid);   // group rows only touched by group

    // ---- epilogue: divide by den, store ----
#pragma unroll
    for (int mt = 0; mt < 2; mt++) {
        int r0 = m0 + mt * 16 + lr;
        int r1 = r0 + 8;
        float inv0 = 1.0f / den_s[r0];
        float inv1 = 1.0f / den_s[r1];
        float* op0 = out + (size_t)(rg0 + r0) * FOUT;
        float* op1 = out + (size_t)(rg0 + r1) * FOUT;
#pragma unroll
        for (int nt = 0; nt < 4; nt++) {
            int col = n0 + nt * 8 + lq * 2;
            *(float2*)(op0 + col) = make_float2(acc[mt * 4 + nt][0] * inv0,
                                                acc[mt * 4 + nt][1] * inv0);
            *(float2*)(op1 + col) = make_float2(acc[mt * 4 + nt][2] * inv1,
                                                acc[mt * 4 + nt][3] * inv1);
        }
    }
}

extern "C" void kernel_launch(void* const* d_in, const int* in_sizes, int n_in,
                              void* d_out, int out_size) {
    const float* h   = (const float*)d_in[0];
    const int*   adj = (const int*)d_in[1];
    const float* Ww  = (const float*)d_in[2];
    const float* Wb  = (const float*)d_in[3];
    const float* aw  = (const float*)d_in[4];
    const float* abp = (const float*)d_in[5];
    float* outp = (float*)d_out;

    cudaFuncSetAttribute(k_attn, cudaFuncAttributeMaxDynamicSharedMemorySize, SMEM_SZ);

    k_gemm<<<MTOT / 64, 256>>>(h, Ww, Wb, aw);
    k_attn<<<MTOT / 128, 512, SMEM_SZ>>>(adj, abp, outp);
}

// round 12
// speedup vs baseline: 1.1111x; 1.0890x over previous
#include <cuda_runtime.h>
#include <cstdint>

#define B_   4
#define N_   4096
#define FIN  256
#define FOUT 128
#define MTOT (B_ * N_)   // 16384

// ---------------- device scratch (no-alloc rule) ----------------
__device__ float g_Wh[(size_t)MTOT * FOUT];   // tf32-rounded values, [row][o]
__device__ float g_src[MTOT];
__device__ float g_dst[MTOT];

// ---------------- helpers ----------------
__device__ __forceinline__ uint32_t f2tf32(float v) {
    uint32_t r;
    asm("cvt.rna.tf32.f32 %0, %1;" : "=r"(r) : "f"(v));
    return r;
}
__device__ __forceinline__ void mma_tf32(float* d, const uint32_t* a, const uint32_t* b) {
    asm volatile(
        "mma.sync.aligned.m16n8k8.row.col.f32.tf32.tf32.f32 "
        "{%0,%1,%2,%3}, {%4,%5,%6,%7}, {%8,%9}, {%0,%1,%2,%3};"
        : "+f"(d[0]), "+f"(d[1]), "+f"(d[2]), "+f"(d[3])
        : "r"(a[0]), "r"(a[1]), "r"(a[2]), "r"(a[3]), "r"(b[0]), "r"(b[1]));
}

// ============================================================
// Kernel 1: Wh = h @ W^T + b ; store tf32-rounded Wh + src/dst
// ============================================================
__global__ void __launch_bounds__(256) k_gemm(
    const float* __restrict__ h, const float* __restrict__ Ww,
    const float* __restrict__ Wb, const float* __restrict__ aw)
{
    __shared__ float hs[32][68];
    __shared__ float ws[32][132];

    const int t  = threadIdx.x;
    const int r0 = blockIdx.x * 64;
    const int to = t & 15, ti = t >> 4;
    const int i0 = ti * 4, o0 = to * 4;

    float acc[4][8];
#pragma unroll
    for (int a = 0; a < 4; a++)
#pragma unroll
        for (int c = 0; c < 8; c++) acc[a][c] = 0.f;

    const int hi = t >> 2, hkb = (t & 3) * 8;
    const int wo = t >> 1, wkb = (t & 1) * 16;

    for (int kt = 0; kt < FIN; kt += 32) {
        const float* hp = h + (size_t)(r0 + hi) * FIN + kt + hkb;
        float4 ha = *(const float4*)(hp);
        float4 hb = *(const float4*)(hp + 4);
        const float* wp = Ww + (size_t)wo * FIN + kt + wkb;
        float4 wa  = *(const float4*)(wp);
        float4 wb4 = *(const float4*)(wp + 4);
        float4 wc  = *(const float4*)(wp + 8);
        float4 wd  = *(const float4*)(wp + 12);

        __syncthreads();

        hs[hkb + 0][hi] = ha.x; hs[hkb + 1][hi] = ha.y;
        hs[hkb + 2][hi] = ha.z; hs[hkb + 3][hi] = ha.w;
        hs[hkb + 4][hi] = hb.x; hs[hkb + 5][hi] = hb.y;
        hs[hkb + 6][hi] = hb.z; hs[hkb + 7][hi] = hb.w;

        ws[wkb +  0][wo] = wa.x;  ws[wkb +  1][wo] = wa.y;
        ws[wkb +  2][wo] = wa.z;  ws[wkb +  3][wo] = wa.w;
        ws[wkb +  4][wo] = wb4.x; ws[wkb +  5][wo] = wb4.y;
        ws[wkb +  6][wo] = wb4.z; ws[wkb +  7][wo] = wb4.w;
        ws[wkb +  8][wo] = wc.x;  ws[wkb +  9][wo] = wc.y;
        ws[wkb + 10][wo] = wc.z;  ws[wkb + 11][wo] = wc.w;
        ws[wkb + 12][wo] = wd.x;  ws[wkb + 13][wo] = wd.y;
        ws[wkb + 14][wo] = wd.z;  ws[wkb + 15][wo] = wd.w;

        __syncthreads();

#pragma unroll 8
        for (int kk = 0; kk < 32; kk++) {
            float4 a4 = *(const float4*)&hs[kk][i0];
            float4 b0 = *(const float4*)&ws[kk][o0];
            float4 b1 = *(const float4*)&ws[kk][o0 + 64];
            float av[4] = {a4.x, a4.y, a4.z, a4.w};
            float bv[8] = {b0.x, b0.y, b0.z, b0.w, b1.x, b1.y, b1.z, b1.w};
#pragma unroll
            for (int ii = 0; ii < 4; ii++)
#pragma unroll
                for (int oo = 0; oo < 8; oo++)
                    acc[ii][oo] = fmaf(av[ii], bv[oo], acc[ii][oo]);
        }
    }

    float bo[8], asv[8], adv[8];
#pragma unroll
    for (int oo = 0; oo < 8; oo++) {
        int o = (oo < 4) ? (o0 + oo) : (64 + o0 + oo - 4);
        bo[oo]  = Wb[o];
        asv[oo] = aw[o];
        adv[oo] = aw[FOUT + o];
    }
    float sp[4], dp[4];
#pragma unroll
    for (int ii = 0; ii < 4; ii++) {
        float s = 0.f, d = 0.f;
        float v[8];
#pragma unroll
        for (int oo = 0; oo < 8; oo++) {
            v[oo] = acc[ii][oo] + bo[oo];
            s = fmaf(v[oo], asv[oo], s);
            d = fmaf(v[oo], adv[oo], d);
        }
        sp[ii] = s; dp[ii] = d;
        const int row = r0 + i0 + ii;
        *(float4*)&g_Wh[(size_t)row * FOUT + o0] =
            make_float4(__uint_as_float(f2tf32(v[0])), __uint_as_float(f2tf32(v[1])),
                        __uint_as_float(f2tf32(v[2])), __uint_as_float(f2tf32(v[3])));
        *(float4*)&g_Wh[(size_t)row * FOUT + 64 + o0] =
            make_float4(__uint_as_float(f2tf32(v[4])), __uint_as_float(f2tf32(v[5])),
                        __uint_as_float(f2tf32(v[6])), __uint_as_float(f2tf32(v[7])));
    }
#pragma unroll
    for (int off = 8; off >= 1; off >>= 1)
#pragma unroll
        for (int ii = 0; ii < 4; ii++) {
            sp[ii] += __shfl_down_sync(0xffffffffu, sp[ii], off);
            dp[ii] += __shfl_down_sync(0xffffffffu, dp[ii], off);
        }
    if (to == 0)
#pragma unroll
        for (int ii = 0; ii < 4; ii++) {
            g_src[r0 + i0 + ii] = sp[ii];
            g_dst[r0 + i0 + ii] = dp[ii];
        }
}

// ============================================================
// Kernel 2: attention via warp-level tf32 mma.sync.
// CTA: 64 rows x 128 cols, 256 threads / 8 warps (32x32 MMA tiles,
// 2x4 grid). 2 CTAs per SM (69KB smem, <=128 regs) so the scheduler
// overlaps one CTA's producer phase with the other's MMA phase.
// Per-warp code identical to R9 (best measured).
// ============================================================
#define KC     64
#define STRA   68                         // A tile stride (floats): 68 % 32 == 4
#define STRB   136                        // B tile stride (floats)
#define SM_DST 0                          // 4096 f = 16384 B
#define SM_DEN 16384                      // 64 f -> pad to 512 B
#define SM_A   16896                      // 64*STRA*4 = 17408 B
#define SM_B   (SM_A + 64 * STRA * 4)
#define SMEM_SZ (SM_B + KC * STRB * 4)    // 69120 B -> 2 CTAs/SM

__global__ void __launch_bounds__(256, 2) k_attn(
    const int* __restrict__ adj, const float* __restrict__ abp,
    float* __restrict__ out)
{
    extern __shared__ char sm[];
    float*    dst_s = (float*)(sm + SM_DST);
    float*    den_s = (float*)(sm + SM_DEN);
    uint32_t* As    = (uint32_t*)(sm + SM_A);   // [m][k], stride STRA
    uint32_t* Bs    = (uint32_t*)(sm + SM_B);   // [k][o], stride STRB

    const int t    = threadIdx.x;
    const int w    = t >> 5, lane = t & 31;
    const int rg0  = blockIdx.x * 64;
    const int b    = rg0 >> 12;
    const int bN   = b << 12;
    const int wr0  = w * 8;                 // this warp's 8 rows (0..63)
    const int cl   = 2 * lane;              // this lane's 2 cols per chunk

    // stage dst for this batch (4096 floats, 256 threads -> 4 float4 each)
    {
        const float4* g  = (const float4*)(g_dst + bN);
        float4*       d4 = (float4*)dst_s;
        for (int q = t; q < N_ / 4; q += 256) d4[q] = g[q];
    }

    const float ab = *abp;
    float srcA[8];
#pragma unroll
    for (int rr = 0; rr < 8; rr++) srcA[rr] = g_src[rg0 + wr0 + rr] + ab;

    // B copy mapping: thread -> Wh row bj (0..63), float4 col bc (0..3), 8 each
    const int bj = t >> 2, bc = t & 3;
    const float4* whp = (const float4*)(g_Wh + (size_t)(bN + bj) * FOUT) + bc;

    // mma mapping: 8 warps, 2x4 grid of 32x32 tiles
    const int m0 = (w >> 2) * 32, n0 = (w & 3) * 32;
    const int lr = lane >> 2, lq = lane & 3;

    float acc[8][4];
#pragma unroll
    for (int x = 0; x < 8; x++)
#pragma unroll
        for (int y = 0; y < 4; y++) acc[x][y] = 0.f;
    float denp[8];
#pragma unroll
    for (int rr = 0; rr < 8; rr++) denp[rr] = 0.f;

    // prefetch chunk 0 (adj coalesced: 256B contiguous per row)
    int2   mA[8];
    float4 vB[8];
#pragma unroll
    for (int rr = 0; rr < 8; rr++)
        mA[rr] = *(const int2*)(adj + (size_t)(rg0 + wr0 + rr) * N_ + cl);
#pragma unroll
    for (int q = 0; q < 8; q++) vB[q] = whp[q * 4];

    __syncthreads();   // dst_s ready

    for (int c = 0; c < N_ / KC; c++) {
        // ---- weights: exp(lrelu(src+dst+ab)), masked; den in fp32 ----
        float2 dv = *(const float2*)&dst_s[c * KC + cl];
        uint2 wpair[8];
#pragma unroll
        for (int rr = 0; rr < 8; rr++) {
            float e0 = srcA[rr] + dv.x, e1 = srcA[rr] + dv.y;
            e0 = (e0 >= 0.f) ? e0 : 0.01f * e0;
            e1 = (e1 >= 0.f) ? e1 : 0.01f * e1;
            float w0 = (mA[rr].x > 0) ? __expf(e0) : 0.f;
            float w1 = (mA[rr].y > 0) ? __expf(e1) : 0.f;
            denp[rr] += w0 + w1;
            wpair[rr] = make_uint2(f2tf32(w0), f2tf32(w1));
        }

        __syncthreads();   // previous chunk's mma reads done

        // ---- store A (weights) [m][k] and B (Wh) [k][o] ----
#pragma unroll
        for (int rr = 0; rr < 8; rr++)
            *(uint2*)&As[(wr0 + rr) * STRA + cl] = wpair[rr];
#pragma unroll
        for (int q = 0; q < 8; q++)
            *(float4*)&Bs[bj * STRB + (bc + 4 * q) * 4] = vB[q];

        // ---- prefetch next chunk (lands during mma) ----
        if (c < N_ / KC - 1) {
#pragma unroll
            for (int rr = 0; rr < 8; rr++)
                mA[rr] = *(const int2*)(adj + (size_t)(rg0 + wr0 + rr) * N_ + (c + 1) * KC + cl);
#pragma unroll
            for (int q = 0; q < 8; q++)
                vB[q] = whp[(size_t)(c + 1) * KC * (FOUT / 4) + q * 4];
        }

        __syncthreads();

        // ---- mma: 8 k-steps of m16n8k8, 32x32 warp tile ----
#pragma unroll
        for (int kk = 0; kk < 8; kk++) {
            uint32_t bf[4][2];
#pragma unroll
            for (int nt = 0; nt < 4; nt++) {
                int o = n0 + nt * 8 + lr;
                bf[nt][0] = Bs[(kk * 8 + lq) * STRB + o];
                bf[nt][1] = Bs[(kk * 8 + lq + 4) * STRB + o];
            }
#pragma unroll
            for (int mt = 0; mt < 2; mt++) {
                uint32_t af[4];
                int m = m0 + mt * 16 + lr;
                af[0] = As[m * STRA + kk * 8 + lq];
                af[1] = As[(m + 8) * STRA + kk * 8 + lq];
                af[2] = As[m * STRA + kk * 8 + lq + 4];
                af[3] = As[(m + 8) * STRA + kk * 8 + lq + 4];
#pragma unroll
                for (int nt = 0; nt < 4; nt++)
                    mma_tf32(acc[mt * 4 + nt], af, bf[nt]);
            }
        }
    }

    // ---- den: full warp reduce (each row's cols live in one warp) ----
#pragma unroll
    for (int rr = 0; rr < 8; rr++) {
#pragma unroll
        for (int off = 16; off >= 1; off >>= 1)
            denp[rr] += __shfl_xor_sync(0xffffffffu, denp[rr], off);
        if (lane == rr) den_s[wr0 + rr] = denp[rr];
    }
    __syncthreads();

    // ---- epilogue: divide by den, store ----
#pragma unroll
    for (int mt = 0; mt < 2; mt++) {
        int r0 = m0 + mt * 16 + lr;
        int r1 = r0 + 8;
        float inv0 = 1.0f / den_s[r0];
        float inv1 = 1.0f / den_s[r1];
        float* op0 = out + (size_t)(rg0 + r0) * FOUT;
        float* op1 = out + (size_t)(rg0 + r1) * FOUT;
#pragma unroll
        for (int nt = 0; nt < 4; nt++) {
            int col = n0 + nt * 8 + lq * 2;
            *(float2*)(op0 + col) = make_float2(acc[mt * 4 + nt][0] * inv0,
                                                acc[mt * 4 + nt][1] * inv0);
            *(float2*)(op1 + col) = make_float2(acc[mt * 4 + nt][2] * inv1,
                                                acc[mt * 4 + nt][3] * inv1);
        }
    }
}

extern "C" void kernel_launch(void* const* d_in, const int* in_sizes, int n_in,
                              void* d_out, int out_size) {
    const float* h   = (const float*)d_in[0];
    const int*   adj = (const int*)d_in[1];
    const float* Ww  = (const float*)d_in[2];
    const float* Wb  = (const float*)d_in[3];
    const float* aw  = (const float*)d_in[4];
    const float* abp = (const float*)d_in[5];
    float* outp = (float*)d_out;

    cudaFuncSetAttribute(k_attn, cudaFuncAttributeMaxDynamicSharedMemorySize, SMEM_SZ);

    k_gemm<<<MTOT / 64, 256>>>(h, Ww, Wb, aw);
    k_attn<<<MTOT / 64, 256, SMEM_SZ>>>(adj, abp, outp);
}